// round 9
// baseline (speedup 1.0000x reference)
#include <cuda_runtime.h>
#include <cuda_bf16.h>

// U1_circuit v7: v6 + tangent-form RX ("fast Givens"): RX pair update is
// 4 ffma2 with t = sn/cs (precomputed in smem); the uniform cs factors are
// deferred and folded into the readout as e *= (prod cs)^2. Cuts the packed
// RX fma-pipe cost from 160 to 96 cyc/gate (~20% of total budget).
//
// inputs: (32,32,32,3) f32   kernel: (8,1,15) f32   out: (32,31,31,8) f32

#define NB 32
#define NH 32
#define NW 32
#define NC 3
#define NY 31
#define NX 31
#define NF 8

#define PIX_PER_BLK 8
#define THREADS 64

typedef unsigned long long u64;

__device__ __forceinline__ u64 pk(float lo, float hi) {
    u64 r; asm("mov.b64 %0, {%1, %2};" : "=l"(r) : "f"(lo), "f"(hi)); return r;
}
__device__ __forceinline__ void unpk(float& lo, float& hi, u64 v) {
    asm("mov.b64 {%0, %1}, %2;" : "=f"(lo), "=f"(hi) : "l"(v));
}
__device__ __forceinline__ u64 bc2(float x) { return pk(x, x); }
__device__ __forceinline__ u64 ffma2(u64 a, u64 b, u64 c) {
    u64 d; asm("fma.rn.f32x2 %0, %1, %2, %3;" : "=l"(d) : "l"(a), "l"(b), "l"(c)); return d;
}
__device__ __forceinline__ u64 fmul2(u64 a, u64 b) {
    u64 d; asm("mul.rn.f32x2 %0, %1, %2;" : "=l"(d) : "l"(a), "l"(b)); return d;
}
__device__ __forceinline__ u64 fadd2(u64 a, u64 b) {
    u64 d; asm("add.rn.f32x2 %0, %1, %2;" : "=l"(d) : "l"(a), "l"(b)); return d;
}
__device__ __forceinline__ u64 fsub2(u64 a, u64 b) {
    u64 d; asm("sub.rn.f32x2 %0, %1, %2;" : "=l"(d) : "l"(a), "l"(b)); return d;
}

__global__ void __launch_bounds__(THREADS)
qsim_kernel(const float* __restrict__ inp,
            const float* __restrict__ ker,
            float* __restrict__ out)
{
    // gates 0..3 : (sn, cs)  (layer-0, used by product init)
    // gates 4..11: (t=sn/cs, cs)  (packed layers, tangent form)
    __shared__ float2 s_rx[PIX_PER_BLK][12];
    __shared__ float2 s_cx[NF][12];           // (br, bi) per filter, gate j*4+g
    __shared__ float2 s_cz[NF][3];            // (lr, li) per filter, layer j

    const int tid  = threadIdx.x;
    const int pix0 = blockIdx.x * PIX_PER_BLK;

    // ---- cooperative precompute: RX angles (8 pixels x 12 gates) ----
#pragma unroll
    for (int k = tid; k < PIX_PER_BLK * 12; k += THREADS) {
        const int pl  = k / 12;
        const int g   = k - pl * 12;
        const int pix = pix0 + pl;
        const int x   = pix % NX;
        const int y   = (pix / NX) % NY;
        const int b   = pix / (NX * NY);
        const int i   = g & 3;
        const int j   = g >> 2;
        const int yy  = y + (i >> 1);
        const int xx  = x + (i & 1);
        const float a = inp[((size_t)(b * NH + yy) * NW + xx) * NC + j];
        float sn, cs;
        sincospif(0.5f * a, &sn, &cs);
        if (g < 4) s_rx[pl][g] = make_float2(sn, cs);
        else       s_rx[pl][g] = make_float2(sn / cs, cs);
    }

    // ---- cooperative precompute: filter params (8 filters x 15) ----
    for (int k = tid; k < NF * 15; k += THREADS) {
        const int f = k / 15;
        const int q = k - f * 15;
        const float p = ker[f * 15 + q];
        float li, lr;
        sincospif(p, &li, &lr);              // lambda = exp(i*pi*p)
        const int j  = q / 5;
        const int q5 = q - j * 5;
        if (q5 < 4) {
            s_cx[f][j * 4 + q5] = make_float2(0.5f * (1.f - lr), -0.5f * li);
        } else {
            s_cz[f][j] = make_float2(lr, li);
        }
    }
    __syncthreads();

    const int pl = tid >> 3;
    const int f  = tid & (NF - 1);

    const int bcb[4] = {8, 4, 2, 1};
    const int btb[4] = {4, 2, 1, 8};

    // ================= scalar phase: lanes identical until first CZ ========
    float ar[16], ai[16];
    {
        const float2 g0 = s_rx[pl][0];   // qubit1 (bit 8)
        const float2 g1 = s_rx[pl][1];   // qubit2 (bit 4)
        const float2 g2 = s_rx[pl][2];   // qubit3 (bit 2)
        const float2 g3 = s_rx[pl][3];   // qubit4 (bit 1)
        const float IS2 = 0.70710678118654752440f;
        float A[4], B[4];
        A[0] = g0.y * g1.y * IS2;  A[1] = g0.y * g1.x * IS2;
        A[2] = g0.x * g1.y * IS2;  A[3] = g0.x * g1.x * IS2;
        B[0] = g2.y * g3.y;        B[1] = g2.y * g3.x;
        B[2] = g2.x * g3.y;        B[3] = g2.x * g3.x;
#pragma unroll
        for (int m = 0; m < 16; m++) {
            const float p = A[m >> 2] * B[m & 3];
            const int k = __popc(m) & 3;
            ar[m] = (k == 0) ? p : ((k == 2) ? -p : 0.f);
            ai[m] = (k == 1) ? -p : ((k == 3) ? p : 0.f);
        }
    }

    // layer-0 CX gates, scalar
#pragma unroll
    for (int g = 0; g < 4; g++) {
        const float2 bb = s_cx[f][g];
        const float br = bb.x, bi = bb.y;
        const int Bc = bcb[g], Bt = btb[g];
#pragma unroll
        for (int m = 0; m < 16; m++) {
            if (!(m & Bc) || (m & Bt)) continue;
            const int m1 = m | Bt;
            const float dr = ar[m1] - ar[m];
            const float di = ai[m1] - ai[m];
            const float er = br * dr - bi * di;
            const float ei = br * di + bi * dr;
            ar[m]  += er;  ai[m]  += ei;
            ar[m1] -= er;  ai[m1] -= ei;
        }
    }

    // layer-0 CZ while packing: hi lane of m>=8 gets *lambda0
    u64 R[16], I[16];
    {
        const float2 ll = s_cz[f][0];
        const float lr = ll.x, li = ll.y;
#pragma unroll
        for (int m = 0; m < 8; m++) {
            R[m] = pk(ar[m], ar[m]);
            I[m] = pk(ai[m], ai[m]);
        }
#pragma unroll
        for (int m = 8; m < 16; m++) {
            const float hr = lr * ar[m] - li * ai[m];
            const float hi = lr * ai[m] + li * ar[m];
            R[m] = pk(ar[m], hr);
            I[m] = pk(ai[m], hi);
        }
    }

    // ================= packed phase: layers 1 and 2 ========================
    float csp = 1.0f;   // deferred product of RX cos factors

#pragma unroll
    for (int j = 1; j < 3; j++) {
        // ---- RX, tangent form: out = (scaled-by-cs-deferred) ----
#pragma unroll
        for (int i = 0; i < 4; i++) {
            const float2 tc = s_rx[pl][j * 4 + i];   // (t, cs)
            const u64 t2  = bc2(tc.x);
            const u64 nt2 = bc2(-tc.x);
            csp *= tc.y;
            const int bit = 8 >> i;
#pragma unroll
            for (int m = 0; m < 16; m++) {
                if (m & bit) continue;
                const int m1 = m | bit;
                const u64 r0 = R[m],  i0 = I[m];
                const u64 r1 = R[m1], i1 = I[m1];
                R[m]  = ffma2(t2,  i1, r0);
                I[m]  = ffma2(nt2, r1, i0);
                R[m1] = ffma2(t2,  i0, r1);
                I[m1] = ffma2(nt2, r0, i1);
            }
        }

        // ---- CX^p: e = b*(y-x); x += e; y -= e ----
#pragma unroll
        for (int g = 0; g < 4; g++) {
            const float2 bb = s_cx[f][j * 4 + g];
            const u64 br2  = bc2(bb.x);
            const u64 bi2  = bc2(bb.y);
            const u64 nbi2 = bc2(-bb.y);
            const int Bc = bcb[g], Bt = btb[g];
#pragma unroll
            for (int m = 0; m < 16; m++) {
                if (!(m & Bc) || (m & Bt)) continue;
                const int m1 = m | Bt;
                const u64 dR = fsub2(R[m1], R[m]);
                const u64 dI = fsub2(I[m1], I[m]);
                const u64 eR = ffma2(br2, dR, fmul2(nbi2, dI));
                const u64 eI = ffma2(br2, dI, fmul2(bi2,  dR));
                R[m]  = fadd2(R[m],  eR);
                I[m]  = fadd2(I[m],  eI);
                R[m1] = fsub2(R[m1], eR);
                I[m1] = fsub2(I[m1], eI);
            }
        }

        // ---- CZ: layer 1 scalar on hi halves; layer 2 folded into readout --
        if (j == 1) {
            const float2 ll = s_cz[f][1];
            const float lr = ll.x, li = ll.y;
#pragma unroll
            for (int m = 8; m < 16; m++) {
                float lo_r, hi_r, lo_i, hi_i;
                unpk(lo_r, hi_r, R[m]);
                unpk(lo_i, hi_i, I[m]);
                const float nhr = lr * hi_r - li * hi_i;
                const float nhi = lr * hi_i + li * hi_r;
                R[m] = pk(lo_r, nhr);
                I[m] = pk(lo_i, nhi);
            }
        }
    }

    // ---- readout (CZ2 + deferred cs product folded in):
    // e = 2*csp^2*[ sum_{m<8} Re(conj(lo) hi) + Re(lambda2 * sum_{m>=8} conj(lo) hi) ]
    float e = 0.f;
#pragma unroll
    for (int m = 0; m < 8; m++) {
        float rl, rh, il, ih;
        unpk(rl, rh, R[m]);
        unpk(il, ih, I[m]);
        e += rl * rh + il * ih;
    }
    float cr = 0.f, ci = 0.f;
#pragma unroll
    for (int m = 8; m < 16; m++) {
        float rl, rh, il, ih;
        unpk(rl, rh, R[m]);
        unpk(il, ih, I[m]);
        cr += rl * rh + il * ih;     // Re(conj(lo)*hi)
        ci += rl * ih - il * rh;     // Im(conj(lo)*hi)
    }
    {
        const float2 ll = s_cz[f][2];
        e += ll.x * cr - ll.y * ci;
    }
    e *= 2.f * csp * csp;
    e = fminf(fmaxf(e, -1.f + 1e-5f), 1.f - 1e-5f);
    out[blockIdx.x * THREADS + tid] = acosf(e) * 0.31830988618379067154f;
}

extern "C" void kernel_launch(void* const* d_in, const int* in_sizes, int n_in,
                              void* d_out, int out_size)
{
    const float* inp = (const float*)d_in[0];
    const float* ker = (const float*)d_in[1];
    float* out = (float*)d_out;
    const int total = NB * NY * NX * NF;        // 246016
    const int blocks = total / THREADS;         // 3844 exactly
    qsim_kernel<<<blocks, THREADS>>>(inp, ker, out);
}

// round 11
// speedup vs baseline: 1.0363x; 1.0363x over previous
#include <cuda_runtime.h>
#include <cuda_bf16.h>

// U1_circuit v9: v8 with the s_fc copy bug fixed (strided copy covers all
// 120 entries; THREADS=64 < 120 made the single-condition copy lose half
// the filter coefficients).
//
// inputs: (32,32,32,3) f32   kernel: (8,1,15) f32   out: (32,31,31,8) f32

#define NB 32
#define NH 32
#define NW 32
#define NC 3
#define NY 31
#define NX 31
#define NF 8

#define PIX_PER_BLK 8
#define THREADS 64

typedef unsigned long long u64;

__device__ __forceinline__ u64 pk(float lo, float hi) {
    u64 r; asm("mov.b64 %0, {%1, %2};" : "=l"(r) : "f"(lo), "f"(hi)); return r;
}
__device__ __forceinline__ void unpk(float& lo, float& hi, u64 v) {
    asm("mov.b64 {%0, %1}, %2;" : "=f"(lo), "=f"(hi) : "l"(v));
}
__device__ __forceinline__ u64 bc2(float x) { return pk(x, x); }
__device__ __forceinline__ u64 ffma2(u64 a, u64 b, u64 c) {
    u64 d; asm("fma.rn.f32x2 %0, %1, %2, %3;" : "=l"(d) : "l"(a), "l"(b), "l"(c)); return d;
}
__device__ __forceinline__ u64 fmul2(u64 a, u64 b) {
    u64 d; asm("mul.rn.f32x2 %0, %1, %2;" : "=l"(d) : "l"(a), "l"(b)); return d;
}
__device__ __forceinline__ u64 fadd2(u64 a, u64 b) {
    u64 d; asm("add.rn.f32x2 %0, %1, %2;" : "=l"(d) : "l"(a), "l"(b)); return d;
}
__device__ __forceinline__ u64 fsub2(u64 a, u64 b) {
    u64 d; asm("sub.rn.f32x2 %0, %1, %2;" : "=l"(d) : "l"(a), "l"(b)); return d;
}

// Filter coefficients: [f*12+g] -> CX (br,bi) for 96 entries,
// [96 + f*3 + j] -> CZ (lr,li) for 24 entries.  120 float2 = 960 B.
__device__ float2 g_fc[120];

__global__ void filter_precompute(const float* __restrict__ ker)
{
    const int k = threadIdx.x;     // 0..119
    if (k >= NF * 15) return;
    const int f = k / 15;
    const int q = k - f * 15;
    const float p = ker[f * 15 + q];
    float li, lr;
    sincospif(p, &li, &lr);        // lambda = exp(i*pi*p)
    const int j  = q / 5;
    const int q5 = q - j * 5;
    if (q5 < 4) {
        g_fc[f * 12 + j * 4 + q5] = make_float2(0.5f * (1.f - lr), -0.5f * li);
    } else {
        g_fc[96 + f * 3 + j] = make_float2(lr, li);
    }
}

__global__ void __launch_bounds__(THREADS, 11)
qsim_kernel(const float* __restrict__ inp,
            float* __restrict__ out)
{
    // gates 0..3 : (sn, cs); gates 4..11: (t=sn/cs, cs)
    __shared__ float2 s_rx[PIX_PER_BLK][12];
    __shared__ float2 s_fc[120];             // filter coefficients (see g_fc)

    const int tid  = threadIdx.x;
    const int pix0 = blockIdx.x * PIX_PER_BLK;

    // ---- copy precomputed filter coefficients (all 120, strided) ----
#pragma unroll
    for (int k = tid; k < 120; k += THREADS) s_fc[k] = g_fc[k];

    // ---- cooperative precompute: RX angles (8 pixels x 12 gates) ----
#pragma unroll
    for (int k = tid; k < PIX_PER_BLK * 12; k += THREADS) {
        const int pl  = k / 12;
        const int g   = k - pl * 12;
        const int pix = pix0 + pl;
        const int x   = pix % NX;
        const int y   = (pix / NX) % NY;
        const int b   = pix / (NX * NY);
        const int i   = g & 3;
        const int j   = g >> 2;
        const int yy  = y + (i >> 1);
        const int xx  = x + (i & 1);
        const float a = inp[((size_t)(b * NH + yy) * NW + xx) * NC + j];
        float sn, cs;
        sincospif(0.5f * a, &sn, &cs);
        if (g < 4) s_rx[pl][g] = make_float2(sn, cs);
        else       s_rx[pl][g] = make_float2(sn / cs, cs);
    }
    __syncthreads();

    const int pl = tid >> 3;
    const int f  = tid & (NF - 1);
    const float2* fc_cx = &s_fc[f * 12];       // [12] CX (br,bi)
    const float2* fc_cz = &s_fc[96 + f * 3];   // [3]  CZ (lr,li)

    const int bcb[4] = {8, 4, 2, 1};
    const int btb[4] = {4, 2, 1, 8};

    // ================= scalar phase: lanes identical until first CZ ========
    float ar[16], ai[16];
    {
        const float2 g0 = s_rx[pl][0];   // qubit1 (bit 8)
        const float2 g1 = s_rx[pl][1];   // qubit2 (bit 4)
        const float2 g2 = s_rx[pl][2];   // qubit3 (bit 2)
        const float2 g3 = s_rx[pl][3];   // qubit4 (bit 1)
        const float IS2 = 0.70710678118654752440f;
        float A[4], B[4];
        A[0] = g0.y * g1.y * IS2;  A[1] = g0.y * g1.x * IS2;
        A[2] = g0.x * g1.y * IS2;  A[3] = g0.x * g1.x * IS2;
        B[0] = g2.y * g3.y;        B[1] = g2.y * g3.x;
        B[2] = g2.x * g3.y;        B[3] = g2.x * g3.x;
#pragma unroll
        for (int m = 0; m < 16; m++) {
            const float p = A[m >> 2] * B[m & 3];
            const int k = __popc(m) & 3;
            ar[m] = (k == 0) ? p : ((k == 2) ? -p : 0.f);
            ai[m] = (k == 1) ? -p : ((k == 3) ? p : 0.f);
        }
    }

    // layer-0 CX gates, scalar
#pragma unroll
    for (int g = 0; g < 4; g++) {
        const float2 bb = fc_cx[g];
        const float br = bb.x, bi = bb.y;
        const int Bc = bcb[g], Bt = btb[g];
#pragma unroll
        for (int m = 0; m < 16; m++) {
            if (!(m & Bc) || (m & Bt)) continue;
            const int m1 = m | Bt;
            const float dr = ar[m1] - ar[m];
            const float di = ai[m1] - ai[m];
            const float er = br * dr - bi * di;
            const float ei = br * di + bi * dr;
            ar[m]  += er;  ai[m]  += ei;
            ar[m1] -= er;  ai[m1] -= ei;
        }
    }

    // layer-0 CZ while packing: hi lane of m>=8 gets *lambda0
    u64 R[16], I[16];
    {
        const float2 ll = fc_cz[0];
        const float lr = ll.x, li = ll.y;
#pragma unroll
        for (int m = 0; m < 8; m++) {
            R[m] = pk(ar[m], ar[m]);
            I[m] = pk(ai[m], ai[m]);
        }
#pragma unroll
        for (int m = 8; m < 16; m++) {
            const float hr = lr * ar[m] - li * ai[m];
            const float hi = lr * ai[m] + li * ar[m];
            R[m] = pk(ar[m], hr);
            I[m] = pk(ai[m], hi);
        }
    }

    // ================= packed phase: layers 1 and 2 ========================
    float csp = 1.0f;   // deferred product of RX cos factors

#pragma unroll
    for (int j = 1; j < 3; j++) {
        // ---- RX, tangent form (cs deferred) ----
#pragma unroll
        for (int i = 0; i < 4; i++) {
            const float2 tc = s_rx[pl][j * 4 + i];   // (t, cs)
            const u64 t2  = bc2(tc.x);
            const u64 nt2 = bc2(-tc.x);
            csp *= tc.y;
            const int bit = 8 >> i;
#pragma unroll
            for (int m = 0; m < 16; m++) {
                if (m & bit) continue;
                const int m1 = m | bit;
                const u64 r0 = R[m],  i0 = I[m];
                const u64 r1 = R[m1], i1 = I[m1];
                R[m]  = ffma2(t2,  i1, r0);
                I[m]  = ffma2(nt2, r1, i0);
                R[m1] = ffma2(t2,  i0, r1);
                I[m1] = ffma2(nt2, r0, i1);
            }
        }

        // ---- CX^p: e = b*(y-x); x += e; y -= e ----
#pragma unroll
        for (int g = 0; g < 4; g++) {
            const float2 bb = fc_cx[j * 4 + g];
            const u64 br2  = bc2(bb.x);
            const u64 bi2  = bc2(bb.y);
            const u64 nbi2 = bc2(-bb.y);
            const int Bc = bcb[g], Bt = btb[g];
#pragma unroll
            for (int m = 0; m < 16; m++) {
                if (!(m & Bc) || (m & Bt)) continue;
                const int m1 = m | Bt;
                const u64 dR = fsub2(R[m1], R[m]);
                const u64 dI = fsub2(I[m1], I[m]);
                const u64 eR = ffma2(br2, dR, fmul2(nbi2, dI));
                const u64 eI = ffma2(br2, dI, fmul2(bi2,  dR));
                R[m]  = fadd2(R[m],  eR);
                I[m]  = fadd2(I[m],  eI);
                R[m1] = fsub2(R[m1], eR);
                I[m1] = fsub2(I[m1], eI);
            }
        }

        // ---- CZ: layer 1 scalar on hi halves; layer 2 folded into readout --
        if (j == 1) {
            const float2 ll = fc_cz[1];
            const float lr = ll.x, li = ll.y;
#pragma unroll
            for (int m = 8; m < 16; m++) {
                float lo_r, hi_r, lo_i, hi_i;
                unpk(lo_r, hi_r, R[m]);
                unpk(lo_i, hi_i, I[m]);
                const float nhr = lr * hi_r - li * hi_i;
                const float nhi = lr * hi_i + li * hi_r;
                R[m] = pk(lo_r, nhr);
                I[m] = pk(lo_i, nhi);
            }
        }
    }

    // ---- readout (CZ2 + deferred cs product folded in) ----
    float e = 0.f;
#pragma unroll
    for (int m = 0; m < 8; m++) {
        float rl, rh, il, ih;
        unpk(rl, rh, R[m]);
        unpk(il, ih, I[m]);
        e += rl * rh + il * ih;
    }
    float cr = 0.f, ci = 0.f;
#pragma unroll
    for (int m = 8; m < 16; m++) {
        float rl, rh, il, ih;
        unpk(rl, rh, R[m]);
        unpk(il, ih, I[m]);
        cr += rl * rh + il * ih;     // Re(conj(lo)*hi)
        ci += rl * ih - il * rh;     // Im(conj(lo)*hi)
    }
    {
        const float2 ll = fc_cz[2];
        e += ll.x * cr - ll.y * ci;
    }
    e *= 2.f * csp * csp;
    e = fminf(fmaxf(e, -1.f + 1e-5f), 1.f - 1e-5f);
    out[blockIdx.x * THREADS + tid] = acosf(e) * 0.31830988618379067154f;
}

extern "C" void kernel_launch(void* const* d_in, const int* in_sizes, int n_in,
                              void* d_out, int out_size)
{
    const float* inp = (const float*)d_in[0];
    const float* ker = (const float*)d_in[1];
    float* out = (float*)d_out;
    filter_precompute<<<1, 128>>>(ker);
    const int total = NB * NY * NX * NF;        // 246016
    const int blocks = total / THREADS;         // 3844 exactly
    qsim_kernel<<<blocks, THREADS>>>(inp, out);
}

// round 12
// speedup vs baseline: 1.1117x; 1.0728x over previous
#include <cuda_runtime.h>
#include <cuda_bf16.h>

// U1_circuit v10: v9 + __launch_bounds__(64, 12) (regs 80 fits 12 CTAs/SM ->
// 24 warps, waves 2.36 -> 2.16) and __fdividef for the tangent precompute.
//
// inputs: (32,32,32,3) f32   kernel: (8,1,15) f32   out: (32,31,31,8) f32

#define NB 32
#define NH 32
#define NW 32
#define NC 3
#define NY 31
#define NX 31
#define NF 8

#define PIX_PER_BLK 8
#define THREADS 64

typedef unsigned long long u64;

__device__ __forceinline__ u64 pk(float lo, float hi) {
    u64 r; asm("mov.b64 %0, {%1, %2};" : "=l"(r) : "f"(lo), "f"(hi)); return r;
}
__device__ __forceinline__ void unpk(float& lo, float& hi, u64 v) {
    asm("mov.b64 {%0, %1}, %2;" : "=f"(lo), "=f"(hi) : "l"(v));
}
__device__ __forceinline__ u64 bc2(float x) { return pk(x, x); }
__device__ __forceinline__ u64 ffma2(u64 a, u64 b, u64 c) {
    u64 d; asm("fma.rn.f32x2 %0, %1, %2, %3;" : "=l"(d) : "l"(a), "l"(b), "l"(c)); return d;
}
__device__ __forceinline__ u64 fmul2(u64 a, u64 b) {
    u64 d; asm("mul.rn.f32x2 %0, %1, %2;" : "=l"(d) : "l"(a), "l"(b)); return d;
}
__device__ __forceinline__ u64 fadd2(u64 a, u64 b) {
    u64 d; asm("add.rn.f32x2 %0, %1, %2;" : "=l"(d) : "l"(a), "l"(b)); return d;
}
__device__ __forceinline__ u64 fsub2(u64 a, u64 b) {
    u64 d; asm("sub.rn.f32x2 %0, %1, %2;" : "=l"(d) : "l"(a), "l"(b)); return d;
}

// Filter coefficients: [f*12+g] -> CX (br,bi) for 96 entries,
// [96 + f*3 + j] -> CZ (lr,li) for 24 entries.  120 float2 = 960 B.
__device__ float2 g_fc[120];

__global__ void filter_precompute(const float* __restrict__ ker)
{
    const int k = threadIdx.x;     // 0..119
    if (k >= NF * 15) return;
    const int f = k / 15;
    const int q = k - f * 15;
    const float p = ker[f * 15 + q];
    float li, lr;
    sincospif(p, &li, &lr);        // lambda = exp(i*pi*p)
    const int j  = q / 5;
    const int q5 = q - j * 5;
    if (q5 < 4) {
        g_fc[f * 12 + j * 4 + q5] = make_float2(0.5f * (1.f - lr), -0.5f * li);
    } else {
        g_fc[96 + f * 3 + j] = make_float2(lr, li);
    }
}

__global__ void __launch_bounds__(THREADS, 12)
qsim_kernel(const float* __restrict__ inp,
            float* __restrict__ out)
{
    // gates 0..3 : (sn, cs); gates 4..11: (t=sn/cs, cs)
    __shared__ float2 s_rx[PIX_PER_BLK][12];
    __shared__ float2 s_fc[120];             // filter coefficients (see g_fc)

    const int tid  = threadIdx.x;
    const int pix0 = blockIdx.x * PIX_PER_BLK;

    // ---- copy precomputed filter coefficients (all 120, strided) ----
#pragma unroll
    for (int k = tid; k < 120; k += THREADS) s_fc[k] = g_fc[k];

    // ---- cooperative precompute: RX angles (8 pixels x 12 gates) ----
#pragma unroll
    for (int k = tid; k < PIX_PER_BLK * 12; k += THREADS) {
        const int pl  = k / 12;
        const int g   = k - pl * 12;
        const int pix = pix0 + pl;
        const int x   = pix % NX;
        const int y   = (pix / NX) % NY;
        const int b   = pix / (NX * NY);
        const int i   = g & 3;
        const int j   = g >> 2;
        const int yy  = y + (i >> 1);
        const int xx  = x + (i & 1);
        const float a = inp[((size_t)(b * NH + yy) * NW + xx) * NC + j];
        float sn, cs;
        sincospif(0.5f * a, &sn, &cs);
        if (g < 4) s_rx[pl][g] = make_float2(sn, cs);
        else       s_rx[pl][g] = make_float2(__fdividef(sn, cs), cs);
    }
    __syncthreads();

    const int pl = tid >> 3;
    const int f  = tid & (NF - 1);
    const float2* fc_cx = &s_fc[f * 12];       // [12] CX (br,bi)
    const float2* fc_cz = &s_fc[96 + f * 3];   // [3]  CZ (lr,li)

    const int bcb[4] = {8, 4, 2, 1};
    const int btb[4] = {4, 2, 1, 8};

    // ================= scalar phase: lanes identical until first CZ ========
    float ar[16], ai[16];
    {
        const float2 g0 = s_rx[pl][0];   // qubit1 (bit 8)
        const float2 g1 = s_rx[pl][1];   // qubit2 (bit 4)
        const float2 g2 = s_rx[pl][2];   // qubit3 (bit 2)
        const float2 g3 = s_rx[pl][3];   // qubit4 (bit 1)
        const float IS2 = 0.70710678118654752440f;
        float A[4], B[4];
        A[0] = g0.y * g1.y * IS2;  A[1] = g0.y * g1.x * IS2;
        A[2] = g0.x * g1.y * IS2;  A[3] = g0.x * g1.x * IS2;
        B[0] = g2.y * g3.y;        B[1] = g2.y * g3.x;
        B[2] = g2.x * g3.y;        B[3] = g2.x * g3.x;
#pragma unroll
        for (int m = 0; m < 16; m++) {
            const float p = A[m >> 2] * B[m & 3];
            const int k = __popc(m) & 3;
            ar[m] = (k == 0) ? p : ((k == 2) ? -p : 0.f);
            ai[m] = (k == 1) ? -p : ((k == 3) ? p : 0.f);
        }
    }

    // layer-0 CX gates, scalar
#pragma unroll
    for (int g = 0; g < 4; g++) {
        const float2 bb = fc_cx[g];
        const float br = bb.x, bi = bb.y;
        const int Bc = bcb[g], Bt = btb[g];
#pragma unroll
        for (int m = 0; m < 16; m++) {
            if (!(m & Bc) || (m & Bt)) continue;
            const int m1 = m | Bt;
            const float dr = ar[m1] - ar[m];
            const float di = ai[m1] - ai[m];
            const float er = br * dr - bi * di;
            const float ei = br * di + bi * dr;
            ar[m]  += er;  ai[m]  += ei;
            ar[m1] -= er;  ai[m1] -= ei;
        }
    }

    // layer-0 CZ while packing: hi lane of m>=8 gets *lambda0
    u64 R[16], I[16];
    {
        const float2 ll = fc_cz[0];
        const float lr = ll.x, li = ll.y;
#pragma unroll
        for (int m = 0; m < 8; m++) {
            R[m] = pk(ar[m], ar[m]);
            I[m] = pk(ai[m], ai[m]);
        }
#pragma unroll
        for (int m = 8; m < 16; m++) {
            const float hr = lr * ar[m] - li * ai[m];
            const float hi = lr * ai[m] + li * ar[m];
            R[m] = pk(ar[m], hr);
            I[m] = pk(ai[m], hi);
        }
    }

    // ================= packed phase: layers 1 and 2 ========================
    float csp = 1.0f;   // deferred product of RX cos factors

#pragma unroll
    for (int j = 1; j < 3; j++) {
        // ---- RX, tangent form (cs deferred) ----
#pragma unroll
        for (int i = 0; i < 4; i++) {
            const float2 tc = s_rx[pl][j * 4 + i];   // (t, cs)
            const u64 t2  = bc2(tc.x);
            const u64 nt2 = bc2(-tc.x);
            csp *= tc.y;
            const int bit = 8 >> i;
#pragma unroll
            for (int m = 0; m < 16; m++) {
                if (m & bit) continue;
                const int m1 = m | bit;
                const u64 r0 = R[m],  i0 = I[m];
                const u64 r1 = R[m1], i1 = I[m1];
                R[m]  = ffma2(t2,  i1, r0);
                I[m]  = ffma2(nt2, r1, i0);
                R[m1] = ffma2(t2,  i0, r1);
                I[m1] = ffma2(nt2, r0, i1);
            }
        }

        // ---- CX^p: e = b*(y-x); x += e; y -= e ----
#pragma unroll
        for (int g = 0; g < 4; g++) {
            const float2 bb = fc_cx[j * 4 + g];
            const u64 br2  = bc2(bb.x);
            const u64 bi2  = bc2(bb.y);
            const u64 nbi2 = bc2(-bb.y);
            const int Bc = bcb[g], Bt = btb[g];
#pragma unroll
            for (int m = 0; m < 16; m++) {
                if (!(m & Bc) || (m & Bt)) continue;
                const int m1 = m | Bt;
                const u64 dR = fsub2(R[m1], R[m]);
                const u64 dI = fsub2(I[m1], I[m]);
                const u64 eR = ffma2(br2, dR, fmul2(nbi2, dI));
                const u64 eI = ffma2(br2, dI, fmul2(bi2,  dR));
                R[m]  = fadd2(R[m],  eR);
                I[m]  = fadd2(I[m],  eI);
                R[m1] = fsub2(R[m1], eR);
                I[m1] = fsub2(I[m1], eI);
            }
        }

        // ---- CZ: layer 1 scalar on hi halves; layer 2 folded into readout --
        if (j == 1) {
            const float2 ll = fc_cz[1];
            const float lr = ll.x, li = ll.y;
#pragma unroll
            for (int m = 8; m < 16; m++) {
                float lo_r, hi_r, lo_i, hi_i;
                unpk(lo_r, hi_r, R[m]);
                unpk(lo_i, hi_i, I[m]);
                const float nhr = lr * hi_r - li * hi_i;
                const float nhi = lr * hi_i + li * hi_r;
                R[m] = pk(lo_r, nhr);
                I[m] = pk(lo_i, nhi);
            }
        }
    }

    // ---- readout (CZ2 + deferred cs product folded in) ----
    float e = 0.f;
#pragma unroll
    for (int m = 0; m < 8; m++) {
        float rl, rh, il, ih;
        unpk(rl, rh, R[m]);
        unpk(il, ih, I[m]);
        e += rl * rh + il * ih;
    }
    float cr = 0.f, ci = 0.f;
#pragma unroll
    for (int m = 8; m < 16; m++) {
        float rl, rh, il, ih;
        unpk(rl, rh, R[m]);
        unpk(il, ih, I[m]);
        cr += rl * rh + il * ih;     // Re(conj(lo)*hi)
        ci += rl * ih - il * rh;     // Im(conj(lo)*hi)
    }
    {
        const float2 ll = fc_cz[2];
        e += ll.x * cr - ll.y * ci;
    }
    e *= 2.f * csp * csp;
    e = fminf(fmaxf(e, -1.f + 1e-5f), 1.f - 1e-5f);
    out[blockIdx.x * THREADS + tid] = acosf(e) * 0.31830988618379067154f;
}

extern "C" void kernel_launch(void* const* d_in, const int* in_sizes, int n_in,
                              void* d_out, int out_size)
{
    const float* inp = (const float*)d_in[0];
    const float* ker = (const float*)d_in[1];
    float* out = (float*)d_out;
    filter_precompute<<<1, 120>>>(ker);
    const int total = NB * NY * NX * NF;        // 246016
    const int blocks = total / THREADS;         // 3844 exactly
    qsim_kernel<<<blocks, THREADS>>>(inp, out);
}